// round 1
// baseline (speedup 1.0000x reference)
#include <cuda_runtime.h>
#include <cuda_bf16.h>

// Problem constants
#define BB   8
#define CC   28
#define HH   256
#define WW   256
#define DG   7
#define CPG  4
#define KH   7
#define NGI  49          // DG*KH
#define PADH 3

// Derived smem layout sizes (in floats)
#define NS_WS1  (NGI*CPG*CC)    // 5488  : stage1 weights  [gi][c][o]
#define NS_W2   (CC*CC*KH)      // 5488  : fused stage2 weights [o][i][j]
#define MIDW    264             // 3 zero + 256 data + 5 zero (16B-aligned rows)
#define NS_MID  (CC*MIDW)       // 7392
#define NS_SAMP (2*CPG*WW)      // 2048 : double-buffered sampled tile

// ---------------------------------------------------------------------------
// Device-global precomputed tables (written by setup kernels each launch).
// ---------------------------------------------------------------------------
__device__ int   d_y0[NGI*HH];
__device__ int   d_y1[NGI*HH];
__device__ float d_wt0[NGI*HH];
__device__ float d_wt1[NGI*HH];
__device__ float d_ws1[NS_WS1];
__device__ float d_W2[NS_W2];
__device__ float d_B2[CC];

// ---------------------------------------------------------------------------
// Setup 1: harmonic sampling tables.
// yp[g,i,h] = (h+1)*(i+1)/(g+1) - 4  (reproduce reference fp32 op order)
// ---------------------------------------------------------------------------
__global__ void setup_tables_kernel() {
    int idx = blockIdx.x * blockDim.x + threadIdx.x;
    if (idx >= NGI * HH) return;
    int gi = idx / HH;
    int h  = idx % HH;
    int g  = gi / KH;
    int i  = gi % KH;

    float fh = (float)h, fg = (float)g, fi = (float)i;
    // reference: off = -i + (h+1)/(g+1)*(i+1) - (h+1);  yp = h - PADH + i + off
    float t   = __fdiv_rn(fh + 1.0f, fg + 1.0f) * (fi + 1.0f);
    float off = -fi + t - (fh + 1.0f);
    float yp  = fh - (float)PADH + fi + off;

    float y0f = floorf(yp);
    float fy  = yp - y0f;
    int   y0i = (int)y0f;

    float v0 = (y0i >= 0 && y0i <= HH - 1) ? 1.0f : 0.0f;
    float v1 = (y0i + 1 >= 0 && y0i + 1 <= HH - 1) ? 1.0f : 0.0f;

    int y0c = y0i < 0 ? 0 : (y0i > HH - 1 ? HH - 1 : y0i);
    int y1i = y0i + 1;
    int y1c = y1i < 0 ? 0 : (y1i > HH - 1 ? HH - 1 : y1i);

    d_y0[idx]  = y0c;
    d_y1[idx]  = y1c;
    d_wt0[idx] = (1.0f - fy) * v0;
    d_wt1[idx] = fy * v1;
}

// ---------------------------------------------------------------------------
// Setup 2: weight reorganization + algebraic fusion of conv1x7 with group mix.
//   ws1[gi][c][o] = weight[o, g*4+c, i, 0]
//   W2[q][i][j]   = sum_g w_m[f,g] * w_t[4g+cc, i, 0, j]   (q = 4f+cc)
//   B2[q]         = sum_g w_m[f,g] * b_t[4g+cc] + b_m[f]
// ---------------------------------------------------------------------------
__global__ void setup_weights_kernel(const float* __restrict__ weight,
                                     const float* __restrict__ w_t,
                                     const float* __restrict__ b_t,
                                     const float* __restrict__ w_m,
                                     const float* __restrict__ b_m) {
    int idx = blockIdx.x * blockDim.x + threadIdx.x;
    if (idx < NS_WS1) {
        int gi = idx / (CPG * CC);
        int r  = idx % (CPG * CC);
        int c  = r / CC;
        int o  = r % CC;
        int g  = gi / KH;
        int i  = gi % KH;
        d_ws1[idx] = weight[(o * CC + g * CPG + c) * KH + i];
    }
    if (idx < NS_W2) {
        int q  = idx / (CC * KH);
        int r2 = idx % (CC * KH);
        int i2 = r2 / KH;
        int j  = r2 % KH;
        int f  = q / CPG;
        int cc = q % CPG;
        float s = 0.0f;
        #pragma unroll
        for (int g = 0; g < DG; g++) {
            s += w_m[f * DG + g] * w_t[((g * CPG + cc) * CC + i2) * KH + j];
        }
        d_W2[idx] = s;
    }
    if (idx < CC) {
        int f  = idx / CPG;
        int cc = idx % CPG;
        float s = b_m[f];
        #pragma unroll
        for (int g = 0; g < DG; g++) {
            s += w_m[f * DG + g] * b_t[g * CPG + cc];
        }
        d_B2[idx] = s;
    }
}

// ---------------------------------------------------------------------------
// Fused main kernel: one block per (b, h) output row.
//   Stage 1: for each of 49 (g,i) taps, cooperatively build the bilinear
//            sampled row samp[c][w] in smem (double-buffered), then a
//            register-tiled (7o x 4w)-per-thread rank-4 update.
//   Stage 2: mid row (28 x 256, zero-padded halo) stays in smem; fused
//            1x7 conv + group-mix via precomputed W2/B2.
// ---------------------------------------------------------------------------
__global__ void __launch_bounds__(256, 2)
harmonic_fused_kernel(const float* __restrict__ x,
                      const float* __restrict__ bias,
                      float* __restrict__ out) {
    extern __shared__ float sm[];
    float* s_ws1  = sm;                       // 5488
    float* s_W2   = s_ws1 + NS_WS1;           // 5488
    float* s_mid  = s_W2 + NS_W2;             // 7392 (16B-aligned rows)
    float* s_samp = s_mid + NS_MID;           // 2048
    float* s_w0   = s_samp + NS_SAMP;         // 49
    float* s_w1   = s_w0 + NGI;               // 49
    float* s_B2   = s_w1 + NGI;               // 28
    float* s_bias = s_B2 + CC;                // 28
    int*   s_y0   = (int*)(s_bias + CC);      // 49
    int*   s_y1   = s_y0 + NGI;               // 49

    const int tid = threadIdx.x;
    const int h   = blockIdx.x & (HH - 1);
    const int b   = blockIdx.x >> 8;

    const int tw = tid & 63;          // 64 w-groups of 4 pixels
    const int to = tid >> 6;          // 4 o-groups of 7 outputs
    const int w0 = tw << 2;

    // ---- block prologue: stage weights & tables ----
    for (int idx = tid; idx < NS_WS1; idx += 256) {
        s_ws1[idx] = d_ws1[idx];
        s_W2[idx]  = d_W2[idx];
    }
    if (tid < NGI) {
        int t = tid * HH + h;
        s_w0[tid] = d_wt0[t];
        s_w1[tid] = d_wt1[t];
        s_y0[tid] = d_y0[t];
        s_y1[tid] = d_y1[t];
    }
    if (tid < CC) {
        s_B2[tid]   = d_B2[tid];
        s_bias[tid] = bias[tid];
    }
    // zero-pad mid halo: 3 left + 5 right per channel row
    if (tid < CC * 8) {
        int o = tid >> 3;
        int p = tid & 7;
        int col = (p < 3) ? p : (256 + p);
        s_mid[o * MIDW + col] = 0.0f;
    }

    const float* xb = x + (size_t)b * CC * HH * WW;

    // ---- prologue: sample tap gi=0 into buffer 0 ----
    {
        int g  = 0;                    // gi = 0
        int r0 = d_y0[0 * HH + h];
        int r1 = d_y1[0 * HH + h];
        float f0 = d_wt0[0 * HH + h];
        float f1 = d_wt1[0 * HH + h];
        const float* pc = xb + (g * CPG) * (HH * WW);
        #pragma unroll
        for (int c = 0; c < CPG; c++) {
            float a0 = __ldg(pc + (c * HH + r0) * WW + tid);
            float a1 = __ldg(pc + (c * HH + r1) * WW + tid);
            s_samp[c * WW + tid] = a0 * f0 + a1 * f1;
        }
    }
    __syncthreads();

    float acc[7][4];
    #pragma unroll
    for (int k = 0; k < 7; k++)
        #pragma unroll
        for (int m = 0; m < 4; m++) acc[k][m] = 0.0f;

    // ---- stage 1 main loop over 49 taps, double-buffered ----
    for (int gi = 0; gi < NGI; gi++) {
        const int cur = gi & 1;

        if (gi < NGI - 1) {
            int gn = gi + 1;
            int g  = gn / KH;
            int r0 = s_y0[gn];
            int r1 = s_y1[gn];
            float f0 = s_w0[gn];
            float f1 = s_w1[gn];
            const float* pc = xb + (g * CPG) * (HH * WW);
            float* dst = s_samp + (cur ^ 1) * (CPG * WW);
            #pragma unroll
            for (int c = 0; c < CPG; c++) {
                float a0 = __ldg(pc + (c * HH + r0) * WW + tid);
                float a1 = __ldg(pc + (c * HH + r1) * WW + tid);
                dst[c * WW + tid] = a0 * f0 + a1 * f1;
            }
        }

        // compute with current buffer
        const float4* sp = (const float4*)(s_samp + cur * (CPG * WW));
        const float* wbase = s_ws1 + gi * (CPG * CC) + to * 7;
        #pragma unroll
        for (int c = 0; c < CPG; c++) {
            float4 v = sp[c * 64 + tw];
            const float* wp = wbase + c * CC;
            #pragma unroll
            for (int k = 0; k < 7; k++) {
                float wv = wp[k];
                acc[k][0] = fmaf(v.x, wv, acc[k][0]);
                acc[k][1] = fmaf(v.y, wv, acc[k][1]);
                acc[k][2] = fmaf(v.z, wv, acc[k][2]);
                acc[k][3] = fmaf(v.w, wv, acc[k][3]);
            }
        }
        __syncthreads();
    }

    // ---- write mid row (+bias) into padded smem ----
    #pragma unroll
    for (int k = 0; k < 7; k++) {
        int o = to * 7 + k;
        float bs = s_bias[o];
        float* mp = s_mid + o * MIDW + 3 + w0;
        mp[0] = acc[k][0] + bs;
        mp[1] = acc[k][1] + bs;
        mp[2] = acc[k][2] + bs;
        mp[3] = acc[k][3] + bs;
    }
    __syncthreads();

    // ---- stage 2: fused 1x7 conv + group mix, all from smem ----
    float acc2[7][4];
    #pragma unroll
    for (int k = 0; k < 7; k++)
        #pragma unroll
        for (int m = 0; m < 4; m++) acc2[k][m] = 0.0f;

    for (int i = 0; i < CC; i++) {
        const float* mrow = s_mid + i * MIDW + w0;   // covers w0-3 .. w0+6
        float4 m03 = *(const float4*)(mrow);
        float4 m47 = *(const float4*)(mrow + 4);
        float2 m89 = *(const float2*)(mrow + 8);
        float m[10] = {m03.x, m03.y, m03.z, m03.w,
                       m47.x, m47.y, m47.z, m47.w,
                       m89.x, m89.y};
        const float* wp2 = s_W2 + (to * 7) * (CC * KH) + i * KH;
        #pragma unroll
        for (int k = 0; k < 7; k++) {
            const float* wk = wp2 + k * (CC * KH);
            #pragma unroll
            for (int j = 0; j < 7; j++) {
                float wv = wk[j];
                acc2[k][0] = fmaf(wv, m[j],     acc2[k][0]);
                acc2[k][1] = fmaf(wv, m[j + 1], acc2[k][1]);
                acc2[k][2] = fmaf(wv, m[j + 2], acc2[k][2]);
                acc2[k][3] = fmaf(wv, m[j + 3], acc2[k][3]);
            }
        }
    }

    // ---- store output row ----
    #pragma unroll
    for (int k = 0; k < 7; k++) {
        int o = to * 7 + k;
        float bq = s_B2[o];
        float4 v;
        v.x = acc2[k][0] + bq;
        v.y = acc2[k][1] + bq;
        v.z = acc2[k][2] + bq;
        v.w = acc2[k][3] + bq;
        *(float4*)(out + ((size_t)(b * CC + o) * HH + h) * WW + w0) = v;
    }
}

// ---------------------------------------------------------------------------
// Launch
// ---------------------------------------------------------------------------
extern "C" void kernel_launch(void* const* d_in, const int* in_sizes, int n_in,
                              void* d_out, int out_size) {
    const float* x      = (const float*)d_in[0];
    const float* weight = (const float*)d_in[1];
    const float* bias   = (const float*)d_in[2];
    const float* w_t    = (const float*)d_in[3];
    const float* b_t    = (const float*)d_in[4];
    const float* w_m    = (const float*)d_in[5];
    const float* b_m    = (const float*)d_in[6];
    float* out = (float*)d_out;

    setup_tables_kernel<<<(NGI * HH + 255) / 256, 256>>>();
    setup_weights_kernel<<<(NS_WS1 + 255) / 256, 256>>>(weight, w_t, b_t, w_m, b_m);

    const int smem_bytes =
        (NS_WS1 + NS_W2 + NS_MID + NS_SAMP + NGI * 2 + CC * 2) * 4  // floats
        + NGI * 2 * 4;                                              // int tables
    cudaFuncSetAttribute(harmonic_fused_kernel,
                         cudaFuncAttributeMaxDynamicSharedMemorySize, smem_bytes);
    harmonic_fused_kernel<<<BB * HH, 256, smem_bytes>>>(x, bias, out);
}